// round 4
// baseline (speedup 1.0000x reference)
#include <cuda_runtime.h>
#include <cstdint>

#define NTOK 4096
#define DIM  1024
#define HDIM 4096
#define NE   8

#define TM 128
#define TN 128
#define TK 16
#define PAD 132   // floats per smem row: 528B, multiple of 16B

__device__ int   g_counts[NE];
__device__ int   g_tlist[NE * NTOK];
__device__ float g_h[(size_t)NTOK * HDIM];   // relu(x@fc)^2 scratch, 64 MB

typedef unsigned long long ull;

// ---------------- f32x2 helpers ----------------
__device__ __forceinline__ ull pack2(float x, float y) {
    ull r;
    asm("mov.b64 %0, {%1,%2};" : "=l"(r) : "f"(x), "f"(y));
    return r;
}
__device__ __forceinline__ void fma2(ull& d, ull a, ull b) {
    asm("fma.rn.f32x2 %0, %1, %2, %0;" : "+l"(d) : "l"(a), "l"(b));
}
__device__ __forceinline__ float2 unpack2(ull v) {
    float2 f;
    asm("mov.b64 {%0,%1}, %2;" : "=f"(f.x), "=f"(f.y) : "l"(v));
    return f;
}

// ---------------------------------------------------------------------------
__global__ void init_counts_kernel() {
    if (threadIdx.x < NE) g_counts[threadIdx.x] = 0;
}

__global__ void router_kernel(const float* __restrict__ x,
                              const float* __restrict__ rw) {
    int warp = (blockIdx.x * blockDim.x + threadIdx.x) >> 5;
    int lane = threadIdx.x & 31;
    if (warp >= NTOK) return;
    const float* xr = x + (size_t)warp * DIM;
    float best = -1e30f;
    int bestE = 0;
#pragma unroll
    for (int e = 0; e < NE; e++) {
        const float* wr = rw + e * DIM;
        float p = 0.f;
        for (int k = lane; k < DIM; k += 32) p += xr[k] * wr[k];
#pragma unroll
        for (int o = 16; o; o >>= 1) p += __shfl_xor_sync(0xffffffffu, p, o);
        if (p > best) { best = p; bestE = e; }   // strict > => first-max (jnp.argmax)
    }
    if (lane == 0) {
        int slot = atomicAdd(&g_counts[bestE], 1);
        g_tlist[bestE * NTOK + slot] = warp;
    }
}

// ---------------------------------------------------------------------------
// Gathered grouped fp32 GEMM using packed fma.rn.f32x2.
// D[128 tokens, 128 n] = A[M,K] @ B, smem operand layout As[k][m], Bs[k][n].
// BTRANS=true : B src elem (k,n) at Bq[k*HDIM + n]  (GEMM1, fc)   -> direct rows
// BTRANS=false: B src elem (n,k) at Bq[n*HDIM + k]  (GEMM2, proj) -> transpose on store
template <int KTOT, bool RELU2, bool BTRANS>
__global__ __launch_bounds__(256) void gemm_f32x2(
    const float* __restrict__ Abase, int astride,
    const float* __restrict__ Bbase,
    float* __restrict__ Obase, int ostride)
{
    constexpr int KT = KTOT / TK;

    __shared__ int   toks[TM];
    __shared__ float As[2][TK][PAD];
    __shared__ float Bs[2][TK][PAD];

    const int e = blockIdx.z;
    const int count = g_counts[e];
    const int m0 = blockIdx.y * TM;
    if (m0 >= count) return;
    const int n0 = blockIdx.x * TN;

    const int tid = threadIdx.x;
    if (tid < TM) {
        int mg = m0 + tid;
        toks[tid] = (mg < count) ? g_tlist[e * NTOK + mg] : -1;
    }
    __syncthreads();

    const float* Bq = Bbase + (size_t)e * DIM * HDIM;

    // ---- load-slot mappings (2 slots of 256 threads each) ----
    // A: 128 rows x 16 k -> 512 float4; idx = it*256+tid; row=idx>>2, kq=(idx&3)*4
    const float* aptr[2];
    int arow[2], akq[2];
#pragma unroll
    for (int it = 0; it < 2; it++) {
        int idx = it * 256 + tid;
        arow[it] = idx >> 2;
        akq[it]  = (idx & 3) * 4;
        int tok = toks[arow[it]];
        aptr[it] = (tok >= 0) ? (Abase + (size_t)tok * astride + akq[it]) : nullptr;
    }
    // B
    const float* bptr[2];
    int brow[2], bkq[2], bkk[2], bn4[2];
#pragma unroll
    for (int it = 0; it < 2; it++) {
        int idx = it * 256 + tid;
        if (BTRANS) {                       // tile [k=16][n=128]
            bkk[it] = idx >> 5;             // 0..15
            bn4[it] = (idx & 31) * 4;       // 0..124
            bptr[it] = Bq + (size_t)bkk[it] * HDIM + n0 + bn4[it];
        } else {                            // src [n][k] -> transpose
            brow[it] = idx >> 2;            // n: 0..127
            bkq[it]  = (idx & 3) * 4;       // k: 0,4,8,12
            bptr[it] = Bq + (size_t)(n0 + brow[it]) * HDIM + bkq[it];
        }
    }

    float4 ra[2], rb[2];
    auto LOAD = [&](int k0) {
#pragma unroll
        for (int it = 0; it < 2; it++) {
            ra[it] = aptr[it] ? *(const float4*)(aptr[it] + k0)
                              : make_float4(0.f, 0.f, 0.f, 0.f);
            if (BTRANS) rb[it] = *(const float4*)(bptr[it] + (size_t)k0 * HDIM);
            else        rb[it] = *(const float4*)(bptr[it] + k0);
        }
    };
    auto STORE = [&](int s) {
#pragma unroll
        for (int it = 0; it < 2; it++) {
            As[s][akq[it] + 0][arow[it]] = ra[it].x;
            As[s][akq[it] + 1][arow[it]] = ra[it].y;
            As[s][akq[it] + 2][arow[it]] = ra[it].z;
            As[s][akq[it] + 3][arow[it]] = ra[it].w;
            if (BTRANS) {
                *(float4*)&Bs[s][bkk[it]][bn4[it]] = rb[it];
            } else {
                Bs[s][bkq[it] + 0][brow[it]] = rb[it].x;
                Bs[s][bkq[it] + 1][brow[it]] = rb[it].y;
                Bs[s][bkq[it] + 2][brow[it]] = rb[it].z;
                Bs[s][bkq[it] + 3][brow[it]] = rb[it].w;
            }
        }
    };

    const int tx = tid & 15;     // n-group: cols tx*8..tx*8+7
    const int ty = tid >> 4;     // m-group: rows ty*8..ty*8+7

    ull acc[8][4];
#pragma unroll
    for (int i = 0; i < 8; i++)
#pragma unroll
        for (int j = 0; j < 4; j++) acc[i][j] = 0ull;

    LOAD(0);
    STORE(0);
    __syncthreads();

    for (int kt = 0; kt < KT; kt++) {
        const int s = kt & 1;
        if (kt + 1 < KT) LOAD((kt + 1) * TK);

#pragma unroll
        for (int kk = 0; kk < TK; kk++) {
            float4 a0 = *(const float4*)&As[s][kk][ty * 8];
            float4 a1 = *(const float4*)&As[s][kk][ty * 8 + 4];
            ulonglong2 b0 = *(const ulonglong2*)&Bs[s][kk][tx * 8];
            ulonglong2 b1 = *(const ulonglong2*)&Bs[s][kk][tx * 8 + 4];
            ull bp[4] = {b0.x, b0.y, b1.x, b1.y};
            ull ap[8] = {pack2(a0.x, a0.x), pack2(a0.y, a0.y),
                         pack2(a0.z, a0.z), pack2(a0.w, a0.w),
                         pack2(a1.x, a1.x), pack2(a1.y, a1.y),
                         pack2(a1.z, a1.z), pack2(a1.w, a1.w)};
#pragma unroll
            for (int i = 0; i < 8; i++)
#pragma unroll
                for (int j = 0; j < 4; j++) fma2(acc[i][j], ap[i], bp[j]);
        }

        if (kt + 1 < KT) {
            __syncthreads();
            STORE(s ^ 1);
            __syncthreads();
        }
    }

    // ---- epilogue: thread owns rows ty*8..+7, cols n0 + tx*8..+7 ----
#pragma unroll
    for (int i = 0; i < 8; i++) {
        int tok = toks[ty * 8 + i];
        if (tok < 0) continue;
        float2 p0 = unpack2(acc[i][0]);
        float2 p1 = unpack2(acc[i][1]);
        float2 p2 = unpack2(acc[i][2]);
        float2 p3 = unpack2(acc[i][3]);
        if (RELU2) {
            p0.x = fmaxf(p0.x, 0.f); p0.x *= p0.x;
            p0.y = fmaxf(p0.y, 0.f); p0.y *= p0.y;
            p1.x = fmaxf(p1.x, 0.f); p1.x *= p1.x;
            p1.y = fmaxf(p1.y, 0.f); p1.y *= p1.y;
            p2.x = fmaxf(p2.x, 0.f); p2.x *= p2.x;
            p2.y = fmaxf(p2.y, 0.f); p2.y *= p2.y;
            p3.x = fmaxf(p3.x, 0.f); p3.x *= p3.x;
            p3.y = fmaxf(p3.y, 0.f); p3.y *= p3.y;
        }
        float* o = Obase + (size_t)tok * ostride + n0 + tx * 8;
        *(float4*)(o)     = make_float4(p0.x, p0.y, p1.x, p1.y);
        *(float4*)(o + 4) = make_float4(p2.x, p2.y, p3.x, p3.y);
    }
}

// ---------------------------------------------------------------------------
extern "C" void kernel_launch(void* const* d_in, const int* in_sizes, int n_in,
                              void* d_out, int out_size) {
    const float* x    = (const float*)d_in[0];
    const float* rw   = (const float*)d_in[1];
    const float* fc   = (const float*)d_in[2];
    const float* proj = (const float*)d_in[3];
    float* out = (float*)d_out;

    init_counts_kernel<<<1, 32>>>();
    router_kernel<<<(NTOK * 32) / 256, 256>>>(x, rw);

    dim3 g1(HDIM / TN, NTOK / TM, NE);   // 32 x 32 x 8, most blocks early-exit
    gemm_f32x2<DIM, true, true><<<g1, 256>>>(x, DIM, fc, g_h, HDIM);

    dim3 g2(DIM / TN, NTOK / TM, NE);    // 8 x 32 x 8
    gemm_f32x2<HDIM, false, false><<<g2, 256>>>(g_h, HDIM, proj, out, DIM);
}